// round 14
// baseline (speedup 1.0000x reference)
#include <cuda.h>
#include <cuda_runtime.h>
#include <cuda_bf16.h>
#include <cuda_fp16.h>
#include <cuda_fp8.h>
#include <cstdint>
#include <math_constants.h>

#if defined(__CUDA_ARCH_FEAT_SM103_ALL) || defined(__CUDA_ARCH_FEAT_SM100_ALL) || defined(__CUDA_ARCH_FEAT_SM101_ALL)
#define HAS_TCGEN05 1
#else
#define HAS_TCGEN05 0
#endif

// ---------------- scratch (device globals; no allocation allowed) ----------
__device__ float g_x[2048 * 1024];
__device__ __nv_bfloat16 g_xn_bf[2048 * 1024];        // xn for downup (bf16)
__device__ uint8_t g_xn_f8[2048 * 1024];              // layer-GEMM A (e4m3)
__device__ __half g_xn_h[2048 * 1024];                // lm_head A (fp16)
__device__ __nv_bfloat16 g_logits_bf[2048 * 16384];
__device__ float g_expr[2048 * 64];
__device__ __half g_lmw_h[32000 * 1024];              // lm_head weights fp16
__device__ uint8_t g_ctxw_f8[4ull * 16384 * 1024];    // ctx weights e4m3 (x16)

// ---------------- constants ---------------------------------------------------
constexpr uint64_t SMEM_DESC_BASE_SW128_C =
    (uint64_t(2)  << 61) | (uint64_t(1) << 46) | (uint64_t(64) << 32) | (uint64_t(1) << 16);
constexpr uint32_t IDESC_F16_C =
    (1u << 4) | (0u << 7) | (0u << 10) | (32u << 17) | (8u << 24);
constexpr float WEIGHT_PRESCALE = 16.0f;

#define MAKE_SMEM_DESC(base_addr) \
    (SMEM_DESC_BASE_SW128_C | ((uint64_t)((base_addr) >> 4) & 0x3FFF))

// ---------------- PTX helpers ----------------------------------------------
__device__ __forceinline__ void mma_sync_tf32(float c[4], const uint32_t a[4], const uint32_t b[2]) {
    asm volatile(
        "mma.sync.aligned.m16n8k8.row.col.f32.tf32.tf32.f32 "
        "{%0,%1,%2,%3}, {%4,%5,%6,%7}, {%8,%9}, {%0,%1,%2,%3};"
        : "+f"(c[0]), "+f"(c[1]), "+f"(c[2]), "+f"(c[3])
        : "r"(a[0]), "r"(a[1]), "r"(a[2]), "r"(a[3]), "r"(b[0]), "r"(b[1]));
}

#define MBARRIER_INIT(addr, cnt) \
    asm volatile("mbarrier.init.shared.b64 [%0], %1;" :: "r"(addr), "r"(cnt) : "memory")

#define MBARRIER_ARRIVE(addr) \
    asm volatile("mbarrier.arrive.shared.b64 _, [%0];" :: "r"(addr) : "memory")

#define MBARRIER_EXPECT_TX(addr, bytes) \
    asm volatile("mbarrier.arrive.expect_tx.shared.b64 _, [%0], %1;" :: "r"(addr), "r"(bytes) : "memory")

#define MBARRIER_WAIT(addr, ph) do {                                          \
    asm volatile(                                                             \
        "{\n\t.reg .pred P1;\n\t"                                             \
        "WAIT_LOOP_%=:\n\t"                                                   \
        "mbarrier.try_wait.parity.acquire.cta.shared::cta.b64 P1, [%0], %1, 0x989680;\n\t" \
        "@P1 bra.uni WAIT_DONE_%=;\n\t"                                       \
        "bra.uni WAIT_LOOP_%=;\n\t"                                           \
        "WAIT_DONE_%=:\n\t}"                                                  \
        :: "r"(addr), "r"(ph) : "memory");                                    \
} while (0)

#define TMA_LOAD_2D(dst, map, cx, cy, mbar)                                   \
    asm volatile(                                                             \
        "cp.async.bulk.tensor.2d.shared::cta.global.tile.mbarrier::complete_tx::bytes " \
        "[%0], [%1, {%2, %3}], [%4];"                                         \
        :: "r"(dst), "l"(map), "r"(cx), "r"(cy), "r"(mbar) : "memory")

#define TCGEN05_ALLOC(sa, n) \
    asm volatile("tcgen05.alloc.cta_group::1.sync.aligned.shared::cta.b32 [%0], %1;" :: "r"(sa), "r"(n) : "memory")
#define TCGEN05_RELINQ() \
    asm volatile("tcgen05.relinquish_alloc_permit.cta_group::1.sync.aligned;")
#define TCGEN05_DEALLOC(t, n) \
    asm volatile("tcgen05.dealloc.cta_group::1.sync.aligned.b32 %0, %1;" :: "r"(t), "r"(n))
#define TCGEN05_COMMIT(mbar) \
    asm volatile("tcgen05.commit.cta_group::1.mbarrier::arrive::one.shared::cluster.b64 [%0];" :: "r"(mbar) : "memory")
#define TCGEN05_FENCE_AFTER() asm volatile("tcgen05.fence::after_thread_sync;" ::: "memory")
#define TCGEN05_FENCE_BEFORE() asm volatile("tcgen05.fence::before_thread_sync;" ::: "memory")
#define TCGEN05_WAIT_LD() asm volatile("tcgen05.wait::ld.sync.aligned;" ::: "memory")

#define TCGEN05_LD_X32(r, tmem)                                               \
    asm volatile(                                                             \
        "tcgen05.ld.sync.aligned.32x32b.x32.b32 "                             \
        "{%0, %1, %2, %3, %4, %5, %6, %7, "                                   \
        " %8, %9, %10, %11, %12, %13, %14, %15, "                             \
        " %16, %17, %18, %19, %20, %21, %22, %23, "                           \
        " %24, %25, %26, %27, %28, %29, %30, %31}, [%32];"                    \
        : "=r"((r)[0]),  "=r"((r)[1]),  "=r"((r)[2]),  "=r"((r)[3]),          \
          "=r"((r)[4]),  "=r"((r)[5]),  "=r"((r)[6]),  "=r"((r)[7]),          \
          "=r"((r)[8]),  "=r"((r)[9]),  "=r"((r)[10]), "=r"((r)[11]),         \
          "=r"((r)[12]), "=r"((r)[13]), "=r"((r)[14]), "=r"((r)[15]),         \
          "=r"((r)[16]), "=r"((r)[17]), "=r"((r)[18]), "=r"((r)[19]),         \
          "=r"((r)[20]), "=r"((r)[21]), "=r"((r)[22]), "=r"((r)[23]),         \
          "=r"((r)[24]), "=r"((r)[25]), "=r"((r)[26]), "=r"((r)[27]),         \
          "=r"((r)[28]), "=r"((r)[29]), "=r"((r)[30]), "=r"((r)[31])          \
        : "r"(tmem))

// Bodies feature-guarded so the compute_103 (no 'a') pass never emits tcgen05.
__device__ __forceinline__ void mma_tc_f16(uint32_t d_tmem, uint64_t a_desc,
                                           uint64_t b_desc, uint32_t idesc, uint32_t en) {
#if HAS_TCGEN05
    asm volatile(
        "{\n\t"
        ".reg .pred p;\n\t"
        "setp.ne.u32 p, %5, 0;\n\t"
        "tcgen05.mma.cta_group::1.kind::f16 [%0], %1, %2, %3, {%4, %4, %4, %4}, p;\n\t"
        "}"
        :: "r"(d_tmem), "l"(a_desc), "l"(b_desc), "r"(idesc), "r"(0u), "r"(en)
        : "memory");
#else
    (void)d_tmem; (void)a_desc; (void)b_desc; (void)idesc; (void)en;
#endif
}

__device__ __forceinline__ void mma_tc_f8(uint32_t d_tmem, uint64_t a_desc,
                                          uint64_t b_desc, uint32_t idesc, uint32_t en) {
#if HAS_TCGEN05
    asm volatile(
        "{\n\t"
        ".reg .pred p;\n\t"
        "setp.ne.u32 p, %5, 0;\n\t"
        "tcgen05.mma.cta_group::1.kind::f8f6f4 [%0], %1, %2, %3, {%4, %4, %4, %4}, p;\n\t"
        "}"
        :: "r"(d_tmem), "l"(a_desc), "l"(b_desc), "r"(idesc), "r"(0u), "r"(en)
        : "memory");
#else
    (void)d_tmem; (void)a_desc; (void)b_desc; (void)idesc; (void)en;
#endif
}

__device__ __forceinline__ uint16_t pack_e4m3x2(float lo, float hi) {
    float2 f = make_float2(lo, hi);
    return (uint16_t)__nv_cvt_float2_to_fp8x2(f, __NV_SATFINITE, __NV_E4M3);
}

// ---------------- kernel: convert lm_head weights to fp16 ------------------
__global__ void k_cvt_h(const float* __restrict__ in, __half* __restrict__ out) {
    size_t i = ((size_t)blockIdx.x * 256 + threadIdx.x) * 8;
    float4 a = *reinterpret_cast<const float4*>(&in[i]);
    float4 b = *reinterpret_cast<const float4*>(&in[i + 4]);
    __half2 p0 = __floats2half2_rn(a.x, a.y);
    __half2 p1 = __floats2half2_rn(a.z, a.w);
    __half2 p2 = __floats2half2_rn(b.x, b.y);
    __half2 p3 = __floats2half2_rn(b.z, b.w);
    uint4 o;
    o.x = *reinterpret_cast<uint32_t*>(&p0);
    o.y = *reinterpret_cast<uint32_t*>(&p1);
    o.z = *reinterpret_cast<uint32_t*>(&p2);
    o.w = *reinterpret_cast<uint32_t*>(&p3);
    *reinterpret_cast<uint4*>(&out[i]) = o;
}

// ---------------- kernel: convert ctx weights to e4m3 (x16) ----------------
__global__ void k_cvt_f8(const float* __restrict__ in, uint8_t* __restrict__ out) {
    size_t i = ((size_t)blockIdx.x * 256 + threadIdx.x) * 8;
    float4 a = *reinterpret_cast<const float4*>(&in[i]);
    float4 b = *reinterpret_cast<const float4*>(&in[i + 4]);
    const float s = WEIGHT_PRESCALE;
    ushort4 o;
    o.x = pack_e4m3x2(a.x * s, a.y * s);
    o.y = pack_e4m3x2(a.z * s, a.w * s);
    o.z = pack_e4m3x2(b.x * s, b.y * s);
    o.w = pack_e4m3x2(b.z * s, b.w * s);
    *reinterpret_cast<ushort4*>(&out[i]) = o;
}

// ---------------- kernel 1: RMSNorm (D=1024) --------------------------------
__global__ void k_rmsnorm(const int* __restrict__ ids, const float* __restrict__ embed,
                          float* __restrict__ x, const float* __restrict__ w,
                          __nv_bfloat16* __restrict__ out_bf,
                          uint8_t* __restrict__ out8,
                          uint16_t* __restrict__ out16, int mode) {
    __shared__ float red[8];
    __shared__ float s_inv;
    int t = blockIdx.x;
    int tid = threadIdx.x;
    int lane = tid & 31, wid = tid >> 5;
    float4 v;
    if (mode == 2) {
        int tok = ids[t];
        v = *reinterpret_cast<const float4*>(&embed[(size_t)tok * 1024 + tid * 4]);
        *reinterpret_cast<float4*>(&x[(size_t)t * 1024 + tid * 4]) = v;
    } else {
        v = *reinterpret_cast<const float4*>(&x[(size_t)t * 1024 + tid * 4]);
    }
    float s = v.x * v.x + v.y * v.y + v.z * v.z + v.w * v.w;
    #pragma unroll
    for (int o = 16; o; o >>= 1) s += __shfl_xor_sync(0xffffffffu, s, o);
    if (lane == 0) red[wid] = s;
    __syncthreads();
    if (tid == 0) {
        float tot = 0.f;
        #pragma unroll
        for (int i = 0; i < 8; i++) tot += red[i];
        s_inv = rsqrtf(tot * (1.0f / 1024.0f) + 1.1920929e-07f);
    }
    __syncthreads();
    float inv = s_inv;
    float4 wv = *reinterpret_cast<const float4*>(&w[tid * 4]);
    float4 o4;
    o4.x = v.x * inv * wv.x;
    o4.y = v.y * inv * wv.y;
    o4.z = v.z * inv * wv.z;
    o4.w = v.w * inv * wv.w;
    if (mode == 1) {
        __half2 p0 = __floats2half2_rn(o4.x, o4.y);
        __half2 p1 = __floats2half2_rn(o4.z, o4.w);
        uint2 ob;
        ob.x = *reinterpret_cast<uint32_t*>(&p0);
        ob.y = *reinterpret_cast<uint32_t*>(&p1);
        *reinterpret_cast<uint2*>(&out16[(size_t)t * 1024 + tid * 4]) = ob;
    } else {
        uint32_t packed = (uint32_t)pack_e4m3x2(o4.x, o4.y) |
                          ((uint32_t)pack_e4m3x2(o4.z, o4.w) << 16);
        *reinterpret_cast<uint32_t*>(&out8[(size_t)t * 1024 + tid * 4]) = packed;
        __nv_bfloat162 b0 = __float22bfloat162_rn(make_float2(o4.x, o4.y));
        __nv_bfloat162 b1 = __float22bfloat162_rn(make_float2(o4.z, o4.w));
        uint2 ob;
        ob.x = *reinterpret_cast<uint32_t*>(&b0);
        ob.y = *reinterpret_cast<uint32_t*>(&b1);
        *reinterpret_cast<uint2*>(&out_bf[(size_t)t * 1024 + tid * 4]) = ob;
    }
}

// ---------------- kernel 2: unified GEMM  C = A*B^T * scale ----------------
// m_off: extra M offset (token-half pipelining).
__global__ __launch_bounds__(288, 1) void k_gemm_tc(
    const __grid_constant__ CUtensorMap tmA,
    const __grid_constant__ CUtensorMap tmB,
    float* __restrict__ C, __nv_bfloat16* __restrict__ Cbf, int N,
    const float* __restrict__ temp_p, int layer, float extra_scale,
    int nit, int kelts, int is_fp8, int out_bf, int m_off) {
    constexpr int STAGES = 3;
    constexpr uint32_t A_BYTES = 256 * 128;
    constexpr uint32_t B_BYTES = 256 * 128;
    extern __shared__ char dsm[];
    __shared__ uint64_t mbar[7];
    __shared__ uint32_t tmem_ptr_sh;

    const int tid = threadIdx.x;
    const int wid = tid >> 5, lane = tid & 31;
    const int bm = blockIdx.y * 256 + m_off;
    const int bn = blockIdx.x * 256;

    uint32_t sraw = (uint32_t)__cvta_generic_to_shared(dsm);
    uint32_t ub = (sraw + 1023u) & ~1023u;
    char* sb_gen = dsm + (ub - sraw);
    uint32_t mb = (uint32_t)__cvta_generic_to_shared(&mbar[0]);

    float scl = extra_scale;
    if (temp_p) scl = extra_scale / fmaxf(temp_p[layer], 0.1f);

    if (tid == 0) {
        #pragma unroll
        for (int s = 0; s < STAGES; s++) MBARRIER_INIT(mb + s * 8, 1);
#if HAS_TCGEN05
        #pragma unroll
        for (int s = 0; s < STAGES; s++) MBARRIER_INIT(mb + (STAGES + s) * 8, 1);
#else
        #pragma unroll
        for (int s = 0; s < STAGES; s++) MBARRIER_INIT(mb + (STAGES + s) * 8, 256);
#endif
        MBARRIER_INIT(mb + 2 * STAGES * 8, 1);
        asm volatile("fence.proxy.async.shared::cta;" ::: "memory");
    }
#if HAS_TCGEN05
    {
        uint32_t tp = (uint32_t)__cvta_generic_to_shared(&tmem_ptr_sh);
        if (wid == 0) { TCGEN05_ALLOC(tp, 512); TCGEN05_RELINQ(); }
    }
#endif
    __syncthreads();

    if (wid == 8) {
        if (lane == 0) {
            uint32_t ph = 1;
            int st = 0;
            const CUtensorMap* pa = &tmA;
            const CUtensorMap* pb = &tmB;
            for (int it = 0; it < nit; it++) {
                MBARRIER_WAIT(mb + (STAGES + st) * 8, ph);
                MBARRIER_EXPECT_TX(mb + st * 8, A_BYTES + B_BYTES);
                TMA_LOAD_2D(ub + st * A_BYTES, pa, it * kelts, bm, mb + st * 8);
                TMA_LOAD_2D(ub + STAGES * A_BYTES + st * B_BYTES, pb, it * kelts, bn, mb + st * 8);
                if (++st == STAGES) { st = 0; ph ^= 1; }
            }
        }
        return;
    }

#if HAS_TCGEN05
    uint32_t tmem;
    asm volatile("ld.shared.b32 %0, [%1];"
                 : "=r"(tmem)
                 : "r"((uint32_t)__cvta_generic_to_shared(&tmem_ptr_sh)));

    if (wid == 0 && lane == 0) {
        uint32_t ph = 0;
        int st = 0;
        for (int it = 0; it < nit; it++) {
            MBARRIER_WAIT(mb + st * 8, ph);
            uint64_t ad = MAKE_SMEM_DESC(ub + st * A_BYTES);
            uint64_t bd = MAKE_SMEM_DESC(ub + STAGES * A_BYTES + st * B_BYTES);
            if (is_fp8) {
                #pragma unroll
                for (int h = 0; h < 2; h++)
                    #pragma unroll
                    for (int k = 0; k < 4; k++)
                        mma_tc_f8(tmem + h * 256, ad + h * 1024 + k * 2, bd + k * 2,
                                  IDESC_F16_C, (uint32_t)(it | k));
            } else {
                #pragma unroll
                for (int h = 0; h < 2; h++)
                    #pragma unroll
                    for (int k = 0; k < 4; k++)
                        mma_tc_f16(tmem + h * 256, ad + h * 1024 + k * 2, bd + k * 2,
                                   IDESC_F16_C, (uint32_t)(it | k));
            }
            TCGEN05_COMMIT(mb + (STAGES + st) * 8);
            if (++st == STAGES) { st = 0; ph ^= 1; }
        }
        TCGEN05_COMMIT(mb + 2 * STAGES * 8);
    }

    MBARRIER_WAIT(mb + 2 * STAGES * 8, 0);
    TCGEN05_FENCE_AFTER();

    {
        int half = wid >> 2;
        size_t rowoff = (size_t)(bm + half * 128 + (wid & 3) * 32 + lane) * N + bn;
        if (out_bf) {
            __nv_bfloat16* crow = Cbf + rowoff;
            #pragma unroll
            for (int cb = 0; cb < 8; cb++) {
                uint32_t r[32];
                TCGEN05_LD_X32(r, tmem + half * 256 + cb * 32);
                TCGEN05_WAIT_LD();
                uint4 o[2];
                uint32_t* ow = reinterpret_cast<uint32_t*>(o);
                #pragma unroll
                for (int j = 0; j < 16; j++) {
                    float2 f = make_float2(__uint_as_float(r[j * 2 + 0]) * scl,
                                           __uint_as_float(r[j * 2 + 1]) * scl);
                    __nv_bfloat162 p = __float22bfloat162_rn(f);
                    ow[j] = *reinterpret_cast<uint32_t*>(&p);
                }
                *reinterpret_cast<uint4*>(&crow[cb * 32]) = o[0];
                *reinterpret_cast<uint4*>(&crow[cb * 32 + 16]) = o[1];
            }
        } else {
            float* crow = C + rowoff;
            #pragma unroll
            for (int cb = 0; cb < 8; cb++) {
                uint32_t r[32];
                TCGEN05_LD_X32(r, tmem + half * 256 + cb * 32);
                TCGEN05_WAIT_LD();
                #pragma unroll
                for (int j = 0; j < 8; j++) {
                    float4 v;
                    v.x = __uint_as_float(r[j * 4 + 0]) * scl;
                    v.y = __uint_as_float(r[j * 4 + 1]) * scl;
                    v.z = __uint_as_float(r[j * 4 + 2]) * scl;
                    v.w = __uint_as_float(r[j * 4 + 3]) * scl;
                    *reinterpret_cast<float4*>(&crow[cb * 32 + j * 4]) = v;
                }
            }
        }
        TCGEN05_FENCE_BEFORE();
    }
    asm volatile("bar.sync 1, 256;" ::: "memory");
    if (wid == 0) TCGEN05_DEALLOC(tmem, 512);
#else
    // ===== mma.sync placeholder (compile-only; 103a cubin is always used) ===
    const uint32_t* sA_all = reinterpret_cast<const uint32_t*>(sb_gen);
    const uint32_t* sB_all = sA_all + STAGES * (A_BYTES / 4);
    int g = lane >> 2, tg = lane & 3;
    int wr = (wid & 3) * 64;
    int wc = (wid >> 2) * 128;
    float c[4][16][4];
    #pragma unroll
    for (int mi = 0; mi < 4; mi++)
        #pragma unroll
        for (int ni = 0; ni < 16; ni++)
            #pragma unroll
            for (int r = 0; r < 4; r++) c[mi][ni][r] = 0.f;
    uint32_t ph = 0;
    int st = 0;
    for (int it = 0; it < nit; it++) {
        MBARRIER_WAIT(mb + st * 8, ph);
        const uint32_t* sA = sA_all + st * (A_BYTES / 4);
        const uint32_t* sB = sB_all + st * (B_BYTES / 4);
        #pragma unroll
        for (int ks = 0; ks < 4; ks++) {
            int c0 = ((2 * ks) ^ g) << 2;
            int c1 = ((2 * ks + 1) ^ g) << 2;
            uint32_t a[4][4], b[16][2];
            #pragma unroll
            for (int mi = 0; mi < 4; mi++) {
                int r0 = wr + mi * 16 + g;
                a[mi][0] = sA[r0 * 32 + c0 + tg];
                a[mi][1] = sA[(r0 + 8) * 32 + c0 + tg];
                a[mi][2] = sA[r0 * 32 + c1 + tg];
                a[mi][3] = sA[(r0 + 8) * 32 + c1 + tg];
            }
            #pragma unroll
            for (int ni = 0; ni < 16; ni++) {
                int rb = wc + ni * 8 + g;
                b[ni][0] = sB[rb * 32 + c0 + tg];
                b[ni][1] = sB[rb * 32 + c1 + tg];
            }
            #pragma unroll
            for (int mi = 0; mi < 4; mi++)
                #pragma unroll
                for (int ni = 0; ni < 16; ni++)
                    mma_sync_tf32(c[mi][ni], a[mi], b[ni]);
        }
        MBARRIER_ARRIVE(mb + (STAGES + st) * 8);
        if (++st == STAGES) { st = 0; ph ^= 1; }
    }
    #pragma unroll
    for (int mi = 0; mi < 4; mi++) {
        #pragma unroll
        for (int ni = 0; ni < 16; ni++) {
            int row0 = bm + wr + mi * 16 + g;
            int col = bn + wc + ni * 8 + tg * 2;
            if (out_bf) {
                __nv_bfloat162 v0 = __float22bfloat162_rn(
                    make_float2(c[mi][ni][0] * scl, c[mi][ni][1] * scl));
                __nv_bfloat162 v1 = __float22bfloat162_rn(
                    make_float2(c[mi][ni][2] * scl, c[mi][ni][3] * scl));
                *reinterpret_cast<__nv_bfloat162*>(&Cbf[(size_t)row0 * N + col]) = v0;
                *reinterpret_cast<__nv_bfloat162*>(&Cbf[(size_t)(row0 + 8) * N + col]) = v1;
            } else {
                float2 v0 = make_float2(c[mi][ni][0] * scl, c[mi][ni][1] * scl);
                float2 v1 = make_float2(c[mi][ni][2] * scl, c[mi][ni][3] * scl);
                *reinterpret_cast<float2*>(&C[(size_t)row0 * N + col]) = v0;
                *reinterpret_cast<float2*>(&C[(size_t)(row0 + 8) * N + col]) = v1;
            }
        }
    }
#endif
}

// ---------------- kernel 3: top-32 + softmax + express (bf16 logits) -------
__global__ __launch_bounds__(256) void k_topk_express(const __nv_bfloat16* __restrict__ logits,
                                                      const float* __restrict__ genes,
                                                      float* __restrict__ expr, int t_off) {
    __shared__ float sv[256][3];
    __shared__ int sp[256][3];
    __shared__ int scnt[256];
    __shared__ float topv[32];
    __shared__ int stopi[32];
    __shared__ float probs[32];
    __shared__ float sred[4][64];

    int t = blockIdx.x + t_off;
    int tid = threadIdx.x;
    const uint4* lrow8 = reinterpret_cast<const uint4*>(logits + (size_t)t * 16384);

    float m0 = -CUDART_INF_F, m1 = -CUDART_INF_F, m2 = -CUDART_INF_F;
    int p0 = 0, p1 = 0, p2 = 0;
    #pragma unroll
    for (int j = 0; j < 8; j++) {
        uint4 v = lrow8[tid + 256 * j];
        int base = 8 * (tid + 256 * j);
        uint32_t w[4] = {v.x, v.y, v.z, v.w};
        #pragma unroll
        for (int q = 0; q < 4; q++) {
            __nv_bfloat162 bp = *reinterpret_cast<__nv_bfloat162*>(&w[q]);
            float e0 = __bfloat162float(bp.x);
            float e1 = __bfloat162float(bp.y);
            int i0 = base + q * 2, i1 = i0 + 1;
            if (e0 > m0) { m2 = m1; p2 = p1; m1 = m0; p1 = p0; m0 = e0; p0 = i0; }
            else if (e0 > m1) { m2 = m1; p2 = p1; m1 = e0; p1 = i0; }
            else if (e0 > m2) { m2 = e0; p2 = i0; }
            if (e1 > m0) { m2 = m1; p2 = p1; m1 = m0; p1 = p0; m0 = e1; p0 = i1; }
            else if (e1 > m1) { m2 = m1; p2 = p1; m1 = e1; p1 = i1; }
            else if (e1 > m2) { m2 = e1; p2 = i1; }
        }
    }
    sv[tid][0] = m0; sv[tid][1] = m1; sv[tid][2] = m2;
    sp[tid][0] = p0; sp[tid][1] = p1; sp[tid][2] = p2;
    scnt[tid] = 0;
    __syncthreads();

    if (tid < 32) {
        for (int k = 0; k < 32; k++) {
            float bv = -CUDART_INF_F;
            int bp = 0x7fffffff, bs = 0;
            #pragma unroll
            for (int q = 0; q < 8; q++) {
                int s = tid * 8 + q;
                int cc = scnt[s];
                float v = sv[s][cc];
                int p = sp[s][cc];
                if (v > bv || (v == bv && p < bp)) { bv = v; bp = p; bs = s; }
            }
            #pragma unroll
            for (int off = 16; off; off >>= 1) {
                float ov = __shfl_xor_sync(0xffffffffu, bv, off);
                int op = __shfl_xor_sync(0xffffffffu, bp, off);
                int os = __shfl_xor_sync(0xffffffffu, bs, off);
                if (ov > bv || (ov == bv && op < bp)) { bv = ov; bp = op; bs = os; }
            }
            int oldc = scnt[bs];
            __syncwarp();
            if (tid == 0) { topv[k] = bv; stopi[k] = bp; scnt[bs] = oldc + 1; }
            __syncwarp();
            if (oldc + 1 == 3) {
                float nv = -CUDART_INF_F;
                int np = 0x7fffffff;
                #pragma unroll
                for (int q = 0; q < 2; q++) {
                    int vIdx = tid * 2 + q;
                    int j = vIdx >> 3, r = vIdx & 7;
                    int idx = 8 * (bs + 256 * j) + r;
                    float e = __bfloat162float(logits[(size_t)t * 16384 + idx]);
                    bool ex = false;
                    for (int kk = 0; kk <= k; kk++)
                        if (stopi[kk] == idx) ex = true;
                    if (!ex && (e > nv || (e == nv && idx < np))) { nv = e; np = idx; }
                }
                #pragma unroll
                for (int off = 16; off; off >>= 1) {
                    float ov = __shfl_xor_sync(0xffffffffu, nv, off);
                    int op = __shfl_xor_sync(0xffffffffu, np, off);
                    if (ov > nv || (ov == nv && op < np)) { nv = ov; np = op; }
                }
                if (tid == 0) { sv[bs][2] = nv; sp[bs][2] = np; scnt[bs] = 2; }
                __syncwarp();
            }
        }
        float pv = expf(topv[tid] - topv[0]);
        float ssum = pv;
        #pragma unroll
        for (int off = 16; off; off >>= 1) ssum += __shfl_xor_sync(0xffffffffu, ssum, off);
        probs[tid] = pv / ssum;
    }
    __syncthreads();

    {
        int d = tid & 63, kq = tid >> 6;
        float acc = 0.f;
        #pragma unroll
        for (int j = 0; j < 8; j++) {
            int k = kq * 8 + j;
            acc += probs[k] * __ldg(&genes[(size_t)stopi[k] * 64 + d]);
        }
        sred[kq][d] = acc;
    }
    __syncthreads();
    if (tid < 64)
        expr[(size_t)t * 64 + tid] = sred[0][tid] + sred[1][tid] + sred[2][tid] + sred[3][tid];
}

// ---------------- kernel 4: down/up + residual update (bf16 xn) ------------
__global__ void k_downup(float* __restrict__ x, const __nv_bfloat16* __restrict__ xn,
                         const float* __restrict__ expr,
                         const float* __restrict__ g2d, const float* __restrict__ g2u,
                         const float* __restrict__ scale_p, int layer, int b_off) {
    __shared__ float sgd[64][65];
    __shared__ float sgu[64][65];
    __shared__ float sex[16][64];

    int t0 = (blockIdx.x + b_off) * 16;
    int d0 = blockIdx.y * 64;
    int tid = threadIdx.x;
    float s = scale_p[layer];

    #pragma unroll
    for (int i = 0; i < 4; i++) {
        int sidx = tid + i * 256;
        int r = sidx >> 4;
        int cc = (sidx & 15) << 2;
        float4 vd = *reinterpret_cast<const float4*>(&g2d[(size_t)(d0 + r) * 64 + cc]);
        sgd[r][cc + 0] = vd.x; sgd[r][cc + 1] = vd.y; sgd[r][cc + 2] = vd.z; sgd[r][cc + 3] = vd.w;
        float4 vu = *reinterpret_cast<const float4*>(&g2u[(size_t)(d0 + r) * 64 + cc]);
        sgu[r][cc + 0] = vu.x; sgu[r][cc + 1] = vu.y; sgu[r][cc + 2] = vu.z; sgu[r][cc + 3] = vu.w;
    }
    {
        int r = tid >> 4;
        int cc = (tid & 15) << 2;
        float4 ve = *reinterpret_cast<const float4*>(&expr[(size_t)(t0 + r) * 64 + cc]);
        sex[r][cc + 0] = ve.x; sex[r][cc + 1] = ve.y; sex[r][cc + 2] = ve.z; sex[r][cc + 3] = ve.w;
    }
    __syncthreads();

    int d = tid & 63;
    int tg = (tid >> 6) * 4;
    float accd[4] = {0.f, 0.f, 0.f, 0.f};
    float accu[4] = {0.f, 0.f, 0.f, 0.f};
    #pragma unroll
    for (int e = 0; e < 64; e++) {
        float gd = sgd[d][e];
        float gu = sgu[d][e];
        #pragma unroll
        for (int tt = 0; tt < 4; tt++) {
            float ex = sex[tg + tt][e];
            accd[tt] += ex * gd;
            accu[tt] += ex * gu;
        }
    }
    #pragma unroll
    for (int tt = 0; tt < 4; tt++) {
        size_t off = (size_t)(t0 + tg + tt) * 1024 + d0 + d;
        float xnv = __bfloat162float(xn[off]);
        x[off] += tanhf(accd[tt]) * xnv * accu[tt] * s;
    }
}

// ---------------- host-side tensormap construction --------------------------
typedef CUresult (*EncodeTiledFn)(
    CUtensorMap*, CUtensorMapDataType, cuuint32_t, void*,
    const cuuint64_t*, const cuuint64_t*, const cuuint32_t*, const cuuint32_t*,
    CUtensorMapInterleave, CUtensorMapSwizzle, CUtensorMapL2promotion,
    CUtensorMapFloatOOBfill);

static void make_map_16(EncodeTiledFn fn, CUtensorMap* m, const void* ptr,
                        uint64_t rows, CUtensorMapDataType dt) {
    cuuint64_t dims[2] = {1024, rows};
    cuuint64_t strides[1] = {1024 * 2};
    cuuint32_t box[2] = {64, 256};
    cuuint32_t estr[2] = {1, 1};
    fn(m, dt, 2, const_cast<void*>(ptr),
       dims, strides, box, estr,
       CU_TENSOR_MAP_INTERLEAVE_NONE, CU_TENSOR_MAP_SWIZZLE_128B,
       CU_TENSOR_MAP_L2_PROMOTION_L2_128B, CU_TENSOR_MAP_FLOAT_OOB_FILL_NONE);
}

static void make_map_8(EncodeTiledFn fn, CUtensorMap* m, const void* ptr,
                       uint64_t rows) {
    cuuint64_t dims[2] = {1024, rows};
    cuuint64_t strides[1] = {1024};
    cuuint32_t box[2] = {128, 256};
    cuuint32_t estr[2] = {1, 1};
    fn(m, CU_TENSOR_MAP_DATA_TYPE_UINT8, 2, const_cast<void*>(ptr),
       dims, strides, box, estr,
       CU_TENSOR_MAP_INTERLEAVE_NONE, CU_TENSOR_MAP_SWIZZLE_128B,
       CU_TENSOR_MAP_L2_PROMOTION_L2_128B, CU_TENSOR_MAP_FLOAT_OOB_FILL_NONE);
}

// ---------------- launch ----------------------------------------------------
extern "C" void kernel_launch(void* const* d_in, const int* in_sizes, int n_in,
                              void* d_out, int out_size) {
    (void)in_sizes; (void)n_in; (void)out_size;
    const int* ids = (const int*)d_in[0];
    const float* embed = (const float*)d_in[1];
    const float* lm_head = (const float*)d_in[2];
    const float* norm_w = (const float*)d_in[3];
    const float* genes = (const float*)d_in[4];
    const float* ctx_w = (const float*)d_in[5];
    const float* temp = (const float*)d_in[6];
    const float* g2d = (const float*)d_in[7];
    const float* g2u = (const float*)d_in[8];
    const float* lnorm = (const float*)d_in[9];
    const float* scale = (const float*)d_in[10];
    float* out = (float*)d_out;

    float *x, *expr;
    __nv_bfloat16 *logbf, *xnbf;
    __half *xnh, *lmwh;
    uint8_t *xnf8, *ctxf8;
    cudaGetSymbolAddress((void**)&x, g_x);
    cudaGetSymbolAddress((void**)&xnbf, g_xn_bf);
    cudaGetSymbolAddress((void**)&xnf8, g_xn_f8);
    cudaGetSymbolAddress((void**)&xnh, g_xn_h);
    cudaGetSymbolAddress((void**)&logbf, g_logits_bf);
    cudaGetSymbolAddress((void**)&expr, g_expr);
    cudaGetSymbolAddress((void**)&lmwh, g_lmw_h);
    cudaGetSymbolAddress((void**)&ctxf8, g_ctxw_f8);

    void* fnp = nullptr;
    cudaDriverEntryPointQueryResult qst;
    cudaGetDriverEntryPoint("cuTensorMapEncodeTiled", &fnp, cudaEnableDefault, &qst);
    EncodeTiledFn enc = (EncodeTiledFn)fnp;

    CUtensorMap tmA_f8, tmB_f8[4], tmA_h, tmHead;
    make_map_8(enc, &tmA_f8, xnf8, 2048);
    for (int i = 0; i < 4; i++)
        make_map_8(enc, &tmB_f8[i], ctxf8 + (size_t)i * 16384 * 1024, 16384);
    make_map_16(enc, &tmA_h, xnh, 2048, CU_TENSOR_MAP_DATA_TYPE_FLOAT16);
    make_map_16(enc, &tmHead, lmwh, 32000, CU_TENSOR_MAP_DATA_TYPE_FLOAT16);

    const int GEMM_SMEM = 1024 + 3 * (256 * 128) + 3 * (256 * 128);  // 197632
    cudaFuncSetAttribute(k_gemm_tc, cudaFuncAttributeMaxDynamicSharedMemorySize, GEMM_SMEM);

    // ---- streams + events (created once) ----
    static cudaStream_t s1 = nullptr, s2 = nullptr;
    static cudaEvent_t ev_fork = nullptr, ev_h = nullptr, ev_f8[4] = {};
    static cudaEvent_t ev_g[4][2] = {}, ev_l[4] = {};
    if (!s1) {
        cudaStreamCreateWithFlags(&s1, cudaStreamNonBlocking);
        cudaStreamCreateWithFlags(&s2, cudaStreamNonBlocking);
        cudaEventCreateWithFlags(&ev_fork, cudaEventDisableTiming);
        cudaEventCreateWithFlags(&ev_h, cudaEventDisableTiming);
        for (int i = 0; i < 4; i++) {
            cudaEventCreateWithFlags(&ev_f8[i], cudaEventDisableTiming);
            cudaEventCreateWithFlags(&ev_g[i][0], cudaEventDisableTiming);
            cudaEventCreateWithFlags(&ev_g[i][1], cudaEventDisableTiming);
            cudaEventCreateWithFlags(&ev_l[i], cudaEventDisableTiming);
        }
    }

    const size_t CHUNK = (size_t)16384 * 1024;
    const int CHUNK_BLOCKS = (int)(CHUNK / 2048);

    cudaEventRecord(ev_fork, 0);
    cudaStreamWaitEvent(s1, ev_fork, 0);
    cudaStreamWaitEvent(s2, ev_fork, 0);

    // side stream s1: all weight converts
    for (int c = 0; c < 4; c++) {
        k_cvt_f8<<<CHUNK_BLOCKS, 256, 0, s1>>>(ctx_w + (size_t)c * CHUNK,
                                               ctxf8 + (size_t)c * CHUNK);
        cudaEventRecord(ev_f8[c], s1);
    }
    k_cvt_h<<<16000, 256, 0, s1>>>(lm_head, lmwh);
    cudaEventRecord(ev_h, s1);

    const float inv_presc = 1.0f / WEIGHT_PRESCALE;
    dim3 gh(16384 / 256, 1024 / 256);   // GEMM half grid: 64 x 4
    dim3 gdh(1024 / 16, 1024 / 64);     // downup half grid: 64 x 16

    for (int i = 0; i < 4; i++) {
        // main: rmsnorm (full 2048 tokens); layer 0 fuses the gather
        k_rmsnorm<<<2048, 256>>>(ids, embed, x, lnorm + (size_t)i * 1024,
                                 xnbf, xnf8, nullptr, i == 0 ? 2 : 0);
        cudaStreamWaitEvent(0, ev_f8[i], 0);
        // main: GEMM halves back-to-back
        k_gemm_tc<<<gh, 288, GEMM_SMEM>>>(tmA_f8, tmB_f8[i], nullptr, logbf, 16384,
                                          temp, i, inv_presc, 8, 128, 1, 1, 0);
        cudaEventRecord(ev_g[i][0], 0);
        k_gemm_tc<<<gh, 288, GEMM_SMEM>>>(tmA_f8, tmB_f8[i], nullptr, logbf, 16384,
                                          temp, i, inv_presc, 8, 128, 1, 1, 1024);
        cudaEventRecord(ev_g[i][1], 0);
        // s2: topk+downup for half 0 overlaps GEMM half 1
        cudaStreamWaitEvent(s2, ev_g[i][0], 0);
        k_topk_express<<<1024, 256, 0, s2>>>(logbf, genes, expr, 0);
        k_downup<<<gdh, 256, 0, s2>>>(x, xnbf, expr, g2d + (size_t)i * 1024 * 64,
                                      g2u + (size_t)i * 1024 * 64, scale, i, 0);
        cudaStreamWaitEvent(s2, ev_g[i][1], 0);
        k_topk_express<<<1024, 256, 0, s2>>>(logbf, genes, expr, 1024);
        k_downup<<<gdh, 256, 0, s2>>>(x, xnbf, expr, g2d + (size_t)i * 1024 * 64,
                                      g2u + (size_t)i * 1024 * 64, scale, i, 64);
        cudaEventRecord(ev_l[i], s2);
        // main waits for this layer's x update before next rmsnorm
        cudaStreamWaitEvent(0, ev_l[i], 0);
    }

    k_rmsnorm<<<2048, 256>>>(ids, embed, x, norm_w, nullptr, nullptr,
                             (uint16_t*)xnh, 1);
    cudaStreamWaitEvent(0, ev_h, 0);
    dim3 g3(32000 / 256, 2048 / 256);
    k_gemm_tc<<<g3, 288, GEMM_SMEM>>>(tmA_h, tmHead, out, nullptr, 32000,
                                      nullptr, 0, 1.0f, 16, 64, 0, 0, 0);
}

// round 15
// speedup vs baseline: 1.0939x; 1.0939x over previous
#include <cuda.h>
#include <cuda_runtime.h>
#include <cuda_bf16.h>
#include <cuda_fp16.h>
#include <cuda_fp8.h>
#include <cstdint>
#include <math_constants.h>

#if defined(__CUDA_ARCH_FEAT_SM103_ALL) || defined(__CUDA_ARCH_FEAT_SM100_ALL) || defined(__CUDA_ARCH_FEAT_SM101_ALL)
#define HAS_TCGEN05 1
#else
#define HAS_TCGEN05 0
#endif

// ---------------- scratch (device globals; no allocation allowed) ----------
__device__ float g_x[2048 * 1024];
__device__ __nv_bfloat16 g_xn_bf[2048 * 1024];        // xn for downup (bf16)
__device__ uint8_t g_xn_f8[2048 * 1024];              // layer-GEMM A (e4m3)
__device__ __half g_xn_h[2048 * 1024];                // lm_head A (fp16)
__device__ __nv_bfloat16 g_logits_bf[2048 * 16384];
__device__ float g_expr[2048 * 64];
__device__ __half g_lmw_h[32000 * 1024];              // lm_head weights fp16
__device__ uint8_t g_ctxw_f8[4ull * 16384 * 1024];    // ctx weights e4m3 (x16)
__device__ __nv_bfloat16 g_g2d_bf[4 * 1024 * 64];     // g2d weights bf16
__device__ __nv_bfloat16 g_g2u_bf[4 * 1024 * 64];     // g2u weights bf16

// ---------------- constants ---------------------------------------------------
constexpr uint64_t SMEM_DESC_BASE_SW128_C =
    (uint64_t(2)  << 61) | (uint64_t(1) << 46) | (uint64_t(64) << 32) | (uint64_t(1) << 16);
constexpr uint32_t IDESC_F16_C =
    (1u << 4) | (0u << 7) | (0u << 10) | (32u << 17) | (8u << 24);
constexpr float WEIGHT_PRESCALE = 16.0f;

#define MAKE_SMEM_DESC(base_addr) \
    (SMEM_DESC_BASE_SW128_C | ((uint64_t)((base_addr) >> 4) & 0x3FFF))

// ---------------- PTX helpers ----------------------------------------------
__device__ __forceinline__ void mma_sync_tf32(float c[4], const uint32_t a[4], const uint32_t b[2]) {
    asm volatile(
        "mma.sync.aligned.m16n8k8.row.col.f32.tf32.tf32.f32 "
        "{%0,%1,%2,%3}, {%4,%5,%6,%7}, {%8,%9}, {%0,%1,%2,%3};"
        : "+f"(c[0]), "+f"(c[1]), "+f"(c[2]), "+f"(c[3])
        : "r"(a[0]), "r"(a[1]), "r"(a[2]), "r"(a[3]), "r"(b[0]), "r"(b[1]));
}

#define MBARRIER_INIT(addr, cnt) \
    asm volatile("mbarrier.init.shared.b64 [%0], %1;" :: "r"(addr), "r"(cnt) : "memory")

#define MBARRIER_ARRIVE(addr) \
    asm volatile("mbarrier.arrive.shared.b64 _, [%0];" :: "r"(addr) : "memory")

#define MBARRIER_EXPECT_TX(addr, bytes) \
    asm volatile("mbarrier.arrive.expect_tx.shared.b64 _, [%0], %1;" :: "r"(addr), "r"(bytes) : "memory")

#define MBARRIER_WAIT(addr, ph) do {                                          \
    asm volatile(                                                             \
        "{\n\t.reg .pred P1;\n\t"                                             \
        "WAIT_LOOP_%=:\n\t"                                                   \
        "mbarrier.try_wait.parity.acquire.cta.shared::cta.b64 P1, [%0], %1, 0x989680;\n\t" \
        "@P1 bra.uni WAIT_DONE_%=;\n\t"                                       \
        "bra.uni WAIT_LOOP_%=;\n\t"                                           \
        "WAIT_DONE_%=:\n\t}"                                                  \
        :: "r"(addr), "r"(ph) : "memory");                                    \
} while (0)

#define TMA_LOAD_2D(dst, map, cx, cy, mbar)                                   \
    asm volatile(                                                             \
        "cp.async.bulk.tensor.2d.shared::cta.global.tile.mbarrier::complete_tx::bytes " \
        "[%0], [%1, {%2, %3}], [%4];"                                         \
        :: "r"(dst), "l"(map), "r"(cx), "r"(cy), "r"(mbar) : "memory")

#define TCGEN05_ALLOC(sa, n) \
    asm volatile("tcgen05.alloc.cta_group::1.sync.aligned.shared::cta.b32 [%0], %1;" :: "r"(sa), "r"(n) : "memory")
#define TCGEN05_RELINQ() \
    asm volatile("tcgen05.relinquish_alloc_permit.cta_group::1.sync.aligned;")
#define TCGEN05_DEALLOC(t, n) \
    asm volatile("tcgen05.dealloc.cta_group::1.sync.aligned.b32 %0, %1;" :: "r"(t), "r"(n))
#define TCGEN05_COMMIT(mbar) \
    asm volatile("tcgen05.commit.cta_group::1.mbarrier::arrive::one.shared::cluster.b64 [%0];" :: "r"(mbar) : "memory")
#define TCGEN05_FENCE_AFTER() asm volatile("tcgen05.fence::after_thread_sync;" ::: "memory")
#define TCGEN05_FENCE_BEFORE() asm volatile("tcgen05.fence::before_thread_sync;" ::: "memory")
#define TCGEN05_WAIT_LD() asm volatile("tcgen05.wait::ld.sync.aligned;" ::: "memory")

#define TCGEN05_LD_X32(r, tmem)                                               \
    asm volatile(                                                             \
        "tcgen05.ld.sync.aligned.32x32b.x32.b32 "                             \
        "{%0, %1, %2, %3, %4, %5, %6, %7, "                                   \
        " %8, %9, %10, %11, %12, %13, %14, %15, "                             \
        " %16, %17, %18, %19, %20, %21, %22, %23, "                           \
        " %24, %25, %26, %27, %28, %29, %30, %31}, [%32];"                    \
        : "=r"((r)[0]),  "=r"((r)[1]),  "=r"((r)[2]),  "=r"((r)[3]),          \
          "=r"((r)[4]),  "=r"((r)[5]),  "=r"((r)[6]),  "=r"((r)[7]),          \
          "=r"((r)[8]),  "=r"((r)[9]),  "=r"((r)[10]), "=r"((r)[11]),         \
          "=r"((r)[12]), "=r"((r)[13]), "=r"((r)[14]), "=r"((r)[15]),         \
          "=r"((r)[16]), "=r"((r)[17]), "=r"((r)[18]), "=r"((r)[19]),         \
          "=r"((r)[20]), "=r"((r)[21]), "=r"((r)[22]), "=r"((r)[23]),         \
          "=r"((r)[24]), "=r"((r)[25]), "=r"((r)[26]), "=r"((r)[27]),         \
          "=r"((r)[28]), "=r"((r)[29]), "=r"((r)[30]), "=r"((r)[31])          \
        : "r"(tmem))

// Bodies feature-guarded so the compute_103 (no 'a') pass never emits tcgen05.
__device__ __forceinline__ void mma_tc_f16(uint32_t d_tmem, uint64_t a_desc,
                                           uint64_t b_desc, uint32_t idesc, uint32_t en) {
#if HAS_TCGEN05
    asm volatile(
        "{\n\t"
        ".reg .pred p;\n\t"
        "setp.ne.u32 p, %5, 0;\n\t"
        "tcgen05.mma.cta_group::1.kind::f16 [%0], %1, %2, %3, {%4, %4, %4, %4}, p;\n\t"
        "}"
        :: "r"(d_tmem), "l"(a_desc), "l"(b_desc), "r"(idesc), "r"(0u), "r"(en)
        : "memory");
#else
    (void)d_tmem; (void)a_desc; (void)b_desc; (void)idesc; (void)en;
#endif
}

__device__ __forceinline__ void mma_tc_f8(uint32_t d_tmem, uint64_t a_desc,
                                          uint64_t b_desc, uint32_t idesc, uint32_t en) {
#if HAS_TCGEN05
    asm volatile(
        "{\n\t"
        ".reg .pred p;\n\t"
        "setp.ne.u32 p, %5, 0;\n\t"
        "tcgen05.mma.cta_group::1.kind::f8f6f4 [%0], %1, %2, %3, {%4, %4, %4, %4}, p;\n\t"
        "}"
        :: "r"(d_tmem), "l"(a_desc), "l"(b_desc), "r"(idesc), "r"(0u), "r"(en)
        : "memory");
#else
    (void)d_tmem; (void)a_desc; (void)b_desc; (void)idesc; (void)en;
#endif
}

__device__ __forceinline__ uint16_t pack_e4m3x2(float lo, float hi) {
    float2 f = make_float2(lo, hi);
    return (uint16_t)__nv_cvt_float2_to_fp8x2(f, __NV_SATFINITE, __NV_E4M3);
}

// ---------------- kernel: convert lm_head weights to fp16 ------------------
__global__ void k_cvt_h(const float* __restrict__ in, __half* __restrict__ out) {
    size_t i = ((size_t)blockIdx.x * 256 + threadIdx.x) * 8;
    float4 a = *reinterpret_cast<const float4*>(&in[i]);
    float4 b = *reinterpret_cast<const float4*>(&in[i + 4]);
    __half2 p0 = __floats2half2_rn(a.x, a.y);
    __half2 p1 = __floats2half2_rn(a.z, a.w);
    __half2 p2 = __floats2half2_rn(b.x, b.y);
    __half2 p3 = __floats2half2_rn(b.z, b.w);
    uint4 o;
    o.x = *reinterpret_cast<uint32_t*>(&p0);
    o.y = *reinterpret_cast<uint32_t*>(&p1);
    o.z = *reinterpret_cast<uint32_t*>(&p2);
    o.w = *reinterpret_cast<uint32_t*>(&p3);
    *reinterpret_cast<uint4*>(&out[i]) = o;
}

// ---------------- kernel: convert fp32 -> bf16 (generic) -------------------
__global__ void k_cvt_bf(const float* __restrict__ in, __nv_bfloat16* __restrict__ out) {
    size_t i = ((size_t)blockIdx.x * 256 + threadIdx.x) * 8;
    float4 a = *reinterpret_cast<const float4*>(&in[i]);
    float4 b = *reinterpret_cast<const float4*>(&in[i + 4]);
    __nv_bfloat162 p0 = __float22bfloat162_rn(make_float2(a.x, a.y));
    __nv_bfloat162 p1 = __float22bfloat162_rn(make_float2(a.z, a.w));
    __nv_bfloat162 p2 = __float22bfloat162_rn(make_float2(b.x, b.y));
    __nv_bfloat162 p3 = __float22bfloat162_rn(make_float2(b.z, b.w));
    uint4 o;
    o.x = *reinterpret_cast<uint32_t*>(&p0);
    o.y = *reinterpret_cast<uint32_t*>(&p1);
    o.z = *reinterpret_cast<uint32_t*>(&p2);
    o.w = *reinterpret_cast<uint32_t*>(&p3);
    *reinterpret_cast<uint4*>(&out[i]) = o;
}

// ---------------- kernel: convert ctx weights to e4m3 (x16) ----------------
__global__ void k_cvt_f8(const float* __restrict__ in, uint8_t* __restrict__ out) {
    size_t i = ((size_t)blockIdx.x * 256 + threadIdx.x) * 8;
    float4 a = *reinterpret_cast<const float4*>(&in[i]);
    float4 b = *reinterpret_cast<const float4*>(&in[i + 4]);
    const float s = WEIGHT_PRESCALE;
    ushort4 o;
    o.x = pack_e4m3x2(a.x * s, a.y * s);
    o.y = pack_e4m3x2(a.z * s, a.w * s);
    o.z = pack_e4m3x2(b.x * s, b.y * s);
    o.w = pack_e4m3x2(b.z * s, b.w * s);
    *reinterpret_cast<ushort4*>(&out[i]) = o;
}

// ---------------- kernel 1: RMSNorm (D=1024) --------------------------------
__global__ void k_rmsnorm(const int* __restrict__ ids, const float* __restrict__ embed,
                          float* __restrict__ x, const float* __restrict__ w,
                          __nv_bfloat16* __restrict__ out_bf,
                          uint8_t* __restrict__ out8,
                          uint16_t* __restrict__ out16, int mode) {
    __shared__ float red[8];
    __shared__ float s_inv;
    int t = blockIdx.x;
    int tid = threadIdx.x;
    int lane = tid & 31, wid = tid >> 5;
    float4 v;
    if (mode == 2) {
        int tok = ids[t];
        v = *reinterpret_cast<const float4*>(&embed[(size_t)tok * 1024 + tid * 4]);
        *reinterpret_cast<float4*>(&x[(size_t)t * 1024 + tid * 4]) = v;
    } else {
        v = *reinterpret_cast<const float4*>(&x[(size_t)t * 1024 + tid * 4]);
    }
    float s = v.x * v.x + v.y * v.y + v.z * v.z + v.w * v.w;
    #pragma unroll
    for (int o = 16; o; o >>= 1) s += __shfl_xor_sync(0xffffffffu, s, o);
    if (lane == 0) red[wid] = s;
    __syncthreads();
    if (tid == 0) {
        float tot = 0.f;
        #pragma unroll
        for (int i = 0; i < 8; i++) tot += red[i];
        s_inv = rsqrtf(tot * (1.0f / 1024.0f) + 1.1920929e-07f);
    }
    __syncthreads();
    float inv = s_inv;
    float4 wv = *reinterpret_cast<const float4*>(&w[tid * 4]);
    float4 o4;
    o4.x = v.x * inv * wv.x;
    o4.y = v.y * inv * wv.y;
    o4.z = v.z * inv * wv.z;
    o4.w = v.w * inv * wv.w;
    if (mode == 1) {
        __half2 p0 = __floats2half2_rn(o4.x, o4.y);
        __half2 p1 = __floats2half2_rn(o4.z, o4.w);
        uint2 ob;
        ob.x = *reinterpret_cast<uint32_t*>(&p0);
        ob.y = *reinterpret_cast<uint32_t*>(&p1);
        *reinterpret_cast<uint2*>(&out16[(size_t)t * 1024 + tid * 4]) = ob;
    } else {
        uint32_t packed = (uint32_t)pack_e4m3x2(o4.x, o4.y) |
                          ((uint32_t)pack_e4m3x2(o4.z, o4.w) << 16);
        *reinterpret_cast<uint32_t*>(&out8[(size_t)t * 1024 + tid * 4]) = packed;
        __nv_bfloat162 b0 = __float22bfloat162_rn(make_float2(o4.x, o4.y));
        __nv_bfloat162 b1 = __float22bfloat162_rn(make_float2(o4.z, o4.w));
        uint2 ob;
        ob.x = *reinterpret_cast<uint32_t*>(&b0);
        ob.y = *reinterpret_cast<uint32_t*>(&b1);
        *reinterpret_cast<uint2*>(&out_bf[(size_t)t * 1024 + tid * 4]) = ob;
    }
}

// ---------------- kernel 2: unified GEMM  C = A*B^T * scale ----------------
__global__ __launch_bounds__(288, 1) void k_gemm_tc(
    const __grid_constant__ CUtensorMap tmA,
    const __grid_constant__ CUtensorMap tmB,
    float* __restrict__ C, __nv_bfloat16* __restrict__ Cbf, int N,
    const float* __restrict__ temp_p, int layer, float extra_scale,
    int nit, int kelts, int is_fp8, int out_bf) {
    constexpr int STAGES = 3;
    constexpr uint32_t A_BYTES = 256 * 128;
    constexpr uint32_t B_BYTES = 256 * 128;
    extern __shared__ char dsm[];
    __shared__ uint64_t mbar[7];
    __shared__ uint32_t tmem_ptr_sh;

    const int tid = threadIdx.x;
    const int wid = tid >> 5, lane = tid & 31;
    const int bm = blockIdx.y * 256;
    const int bn = blockIdx.x * 256;

    uint32_t sraw = (uint32_t)__cvta_generic_to_shared(dsm);
    uint32_t ub = (sraw + 1023u) & ~1023u;
    char* sb_gen = dsm + (ub - sraw);
    uint32_t mb = (uint32_t)__cvta_generic_to_shared(&mbar[0]);

    float scl = extra_scale;
    if (temp_p) scl = extra_scale / fmaxf(temp_p[layer], 0.1f);

    if (tid == 0) {
        #pragma unroll
        for (int s = 0; s < STAGES; s++) MBARRIER_INIT(mb + s * 8, 1);
#if HAS_TCGEN05
        #pragma unroll
        for (int s = 0; s < STAGES; s++) MBARRIER_INIT(mb + (STAGES + s) * 8, 1);
#else
        #pragma unroll
        for (int s = 0; s < STAGES; s++) MBARRIER_INIT(mb + (STAGES + s) * 8, 256);
#endif
        MBARRIER_INIT(mb + 2 * STAGES * 8, 1);
        asm volatile("fence.proxy.async.shared::cta;" ::: "memory");
    }
#if HAS_TCGEN05
    {
        uint32_t tp = (uint32_t)__cvta_generic_to_shared(&tmem_ptr_sh);
        if (wid == 0) { TCGEN05_ALLOC(tp, 512); TCGEN05_RELINQ(); }
    }
#endif
    __syncthreads();

    if (wid == 8) {
        if (lane == 0) {
            uint32_t ph = 1;
            int st = 0;
            const CUtensorMap* pa = &tmA;
            const CUtensorMap* pb = &tmB;
            for (int it = 0; it < nit; it++) {
                MBARRIER_WAIT(mb + (STAGES + st) * 8, ph);
                MBARRIER_EXPECT_TX(mb + st * 8, A_BYTES + B_BYTES);
                TMA_LOAD_2D(ub + st * A_BYTES, pa, it * kelts, bm, mb + st * 8);
                TMA_LOAD_2D(ub + STAGES * A_BYTES + st * B_BYTES, pb, it * kelts, bn, mb + st * 8);
                if (++st == STAGES) { st = 0; ph ^= 1; }
            }
        }
        return;
    }

#if HAS_TCGEN05
    uint32_t tmem;
    asm volatile("ld.shared.b32 %0, [%1];"
                 : "=r"(tmem)
                 : "r"((uint32_t)__cvta_generic_to_shared(&tmem_ptr_sh)));

    if (wid == 0 && lane == 0) {
        uint32_t ph = 0;
        int st = 0;
        for (int it = 0; it < nit; it++) {
            MBARRIER_WAIT(mb + st * 8, ph);
            uint64_t ad = MAKE_SMEM_DESC(ub + st * A_BYTES);
            uint64_t bd = MAKE_SMEM_DESC(ub + STAGES * A_BYTES + st * B_BYTES);
            if (is_fp8) {
                #pragma unroll
                for (int h = 0; h < 2; h++)
                    #pragma unroll
                    for (int k = 0; k < 4; k++)
                        mma_tc_f8(tmem + h * 256, ad + h * 1024 + k * 2, bd + k * 2,
                                  IDESC_F16_C, (uint32_t)(it | k));
            } else {
                #pragma unroll
                for (int h = 0; h < 2; h++)
                    #pragma unroll
                    for (int k = 0; k < 4; k++)
                        mma_tc_f16(tmem + h * 256, ad + h * 1024 + k * 2, bd + k * 2,
                                   IDESC_F16_C, (uint32_t)(it | k));
            }
            TCGEN05_COMMIT(mb + (STAGES + st) * 8);
            if (++st == STAGES) { st = 0; ph ^= 1; }
        }
        TCGEN05_COMMIT(mb + 2 * STAGES * 8);
    }

    MBARRIER_WAIT(mb + 2 * STAGES * 8, 0);
    TCGEN05_FENCE_AFTER();

    {
        int half = wid >> 2;
        size_t rowoff = (size_t)(bm + half * 128 + (wid & 3) * 32 + lane) * N + bn;
        if (out_bf) {
            __nv_bfloat16* crow = Cbf + rowoff;
            #pragma unroll
            for (int cb = 0; cb < 8; cb++) {
                uint32_t r[32];
                TCGEN05_LD_X32(r, tmem + half * 256 + cb * 32);
                TCGEN05_WAIT_LD();
                uint4 o[2];
                uint32_t* ow = reinterpret_cast<uint32_t*>(o);
                #pragma unroll
                for (int j = 0; j < 16; j++) {
                    float2 f = make_float2(__uint_as_float(r[j * 2 + 0]) * scl,
                                           __uint_as_float(r[j * 2 + 1]) * scl);
                    __nv_bfloat162 p = __float22bfloat162_rn(f);
                    ow[j] = *reinterpret_cast<uint32_t*>(&p);
                }
                *reinterpret_cast<uint4*>(&crow[cb * 32]) = o[0];
                *reinterpret_cast<uint4*>(&crow[cb * 32 + 16]) = o[1];
            }
        } else {
            float* crow = C + rowoff;
            #pragma unroll
            for (int cb = 0; cb < 8; cb++) {
                uint32_t r[32];
                TCGEN05_LD_X32(r, tmem + half * 256 + cb * 32);
                TCGEN05_WAIT_LD();
                #pragma unroll
                for (int j = 0; j < 8; j++) {
                    float4 v;
                    v.x = __uint_as_float(r[j * 4 + 0]) * scl;
                    v.y = __uint_as_float(r[j * 4 + 1]) * scl;
                    v.z = __uint_as_float(r[j * 4 + 2]) * scl;
                    v.w = __uint_as_float(r[j * 4 + 3]) * scl;
                    *reinterpret_cast<float4*>(&crow[cb * 32 + j * 4]) = v;
                }
            }
        }
        TCGEN05_FENCE_BEFORE();
    }
    asm volatile("bar.sync 1, 256;" ::: "memory");
    if (wid == 0) TCGEN05_DEALLOC(tmem, 512);
#else
    // ===== mma.sync placeholder (compile-only; 103a cubin is always used) ===
    const uint32_t* sA_all = reinterpret_cast<const uint32_t*>(sb_gen);
    const uint32_t* sB_all = sA_all + STAGES * (A_BYTES / 4);
    int g = lane >> 2, tg = lane & 3;
    int wr = (wid & 3) * 64;
    int wc = (wid >> 2) * 128;
    float c[4][16][4];
    #pragma unroll
    for (int mi = 0; mi < 4; mi++)
        #pragma unroll
        for (int ni = 0; ni < 16; ni++)
            #pragma unroll
            for (int r = 0; r < 4; r++) c[mi][ni][r] = 0.f;
    uint32_t ph = 0;
    int st = 0;
    for (int it = 0; it < nit; it++) {
        MBARRIER_WAIT(mb + st * 8, ph);
        const uint32_t* sA = sA_all + st * (A_BYTES / 4);
        const uint32_t* sB = sB_all + st * (B_BYTES / 4);
        #pragma unroll
        for (int ks = 0; ks < 4; ks++) {
            int c0 = ((2 * ks) ^ g) << 2;
            int c1 = ((2 * ks + 1) ^ g) << 2;
            uint32_t a[4][4], b[16][2];
            #pragma unroll
            for (int mi = 0; mi < 4; mi++) {
                int r0 = wr + mi * 16 + g;
                a[mi][0] = sA[r0 * 32 + c0 + tg];
                a[mi][1] = sA[(r0 + 8) * 32 + c0 + tg];
                a[mi][2] = sA[r0 * 32 + c1 + tg];
                a[mi][3] = sA[(r0 + 8) * 32 + c1 + tg];
            }
            #pragma unroll
            for (int ni = 0; ni < 16; ni++) {
                int rb = wc + ni * 8 + g;
                b[ni][0] = sB[rb * 32 + c0 + tg];
                b[ni][1] = sB[rb * 32 + c1 + tg];
            }
            #pragma unroll
            for (int mi = 0; mi < 4; mi++)
                #pragma unroll
                for (int ni = 0; ni < 16; ni++)
                    mma_sync_tf32(c[mi][ni], a[mi], b[ni]);
        }
        MBARRIER_ARRIVE(mb + (STAGES + st) * 8);
        if (++st == STAGES) { st = 0; ph ^= 1; }
    }
    #pragma unroll
    for (int mi = 0; mi < 4; mi++) {
        #pragma unroll
        for (int ni = 0; ni < 16; ni++) {
            int row0 = bm + wr + mi * 16 + g;
            int col = bn + wc + ni * 8 + tg * 2;
            if (out_bf) {
                __nv_bfloat162 v0 = __float22bfloat162_rn(
                    make_float2(c[mi][ni][0] * scl, c[mi][ni][1] * scl));
                __nv_bfloat162 v1 = __float22bfloat162_rn(
                    make_float2(c[mi][ni][2] * scl, c[mi][ni][3] * scl));
                *reinterpret_cast<__nv_bfloat162*>(&Cbf[(size_t)row0 * N + col]) = v0;
                *reinterpret_cast<__nv_bfloat162*>(&Cbf[(size_t)(row0 + 8) * N + col]) = v1;
            } else {
                float2 v0 = make_float2(c[mi][ni][0] * scl, c[mi][ni][1] * scl);
                float2 v1 = make_float2(c[mi][ni][2] * scl, c[mi][ni][3] * scl);
                *reinterpret_cast<float2*>(&C[(size_t)row0 * N + col]) = v0;
                *reinterpret_cast<float2*>(&C[(size_t)(row0 + 8) * N + col]) = v1;
            }
        }
    }
#endif
}

// ---------------- kernel 3: top-32 + softmax + express (bf16 logits) -------
__global__ __launch_bounds__(256) void k_topk_express(const __nv_bfloat16* __restrict__ logits,
                                                      const float* __restrict__ genes,
                                                      float* __restrict__ expr) {
    __shared__ float sv[256][3];
    __shared__ int sp[256][3];
    __shared__ int scnt[256];
    __shared__ float topv[32];
    __shared__ int stopi[32];
    __shared__ float probs[32];
    __shared__ float sred[4][64];

    int t = blockIdx.x;
    int tid = threadIdx.x;
    const uint4* lrow8 = reinterpret_cast<const uint4*>(logits + (size_t)t * 16384);

    float m0 = -CUDART_INF_F, m1 = -CUDART_INF_F, m2 = -CUDART_INF_F;
    int p0 = 0, p1 = 0, p2 = 0;
    #pragma unroll
    for (int j = 0; j < 8; j++) {
        uint4 v = lrow8[tid + 256 * j];
        int base = 8 * (tid + 256 * j);
        uint32_t w[4] = {v.x, v.y, v.z, v.w};
        #pragma unroll
        for (int q = 0; q < 4; q++) {
            __nv_bfloat162 bp = *reinterpret_cast<__nv_bfloat162*>(&w[q]);
            float e0 = __bfloat162float(bp.x);
            float e1 = __bfloat162float(bp.y);
            int i0 = base + q * 2, i1 = i0 + 1;
            if (e0 > m0) { m2 = m1; p2 = p1; m1 = m0; p1 = p0; m0 = e0; p0 = i0; }
            else if (e0 > m1) { m2 = m1; p2 = p1; m1 = e0; p1 = i0; }
            else if (e0 > m2) { m2 = e0; p2 = i0; }
            if (e1 > m0) { m2 = m1; p2 = p1; m1 = m0; p1 = p0; m0 = e1; p0 = i1; }
            else if (e1 > m1) { m2 = m1; p2 = p1; m1 = e1; p1 = i1; }
            else if (e1 > m2) { m2 = e1; p2 = i1; }
        }
    }
    sv[tid][0] = m0; sv[tid][1] = m1; sv[tid][2] = m2;
    sp[tid][0] = p0; sp[tid][1] = p1; sp[tid][2] = p2;
    scnt[tid] = 0;
    __syncthreads();

    if (tid < 32) {
        for (int k = 0; k < 32; k++) {
            float bv = -CUDART_INF_F;
            int bp = 0x7fffffff, bs = 0;
            #pragma unroll
            for (int q = 0; q < 8; q++) {
                int s = tid * 8 + q;
                int cc = scnt[s];
                float v = sv[s][cc];
                int p = sp[s][cc];
                if (v > bv || (v == bv && p < bp)) { bv = v; bp = p; bs = s; }
            }
            #pragma unroll
            for (int off = 16; off; off >>= 1) {
                float ov = __shfl_xor_sync(0xffffffffu, bv, off);
                int op = __shfl_xor_sync(0xffffffffu, bp, off);
                int os = __shfl_xor_sync(0xffffffffu, bs, off);
                if (ov > bv || (ov == bv && op < bp)) { bv = ov; bp = op; bs = os; }
            }
            int oldc = scnt[bs];
            __syncwarp();
            if (tid == 0) { topv[k] = bv; stopi[k] = bp; scnt[bs] = oldc + 1; }
            __syncwarp();
            if (oldc + 1 == 3) {
                float nv = -CUDART_INF_F;
                int np = 0x7fffffff;
                #pragma unroll
                for (int q = 0; q < 2; q++) {
                    int vIdx = tid * 2 + q;
                    int j = vIdx >> 3, r = vIdx & 7;
                    int idx = 8 * (bs + 256 * j) + r;
                    float e = __bfloat162float(logits[(size_t)t * 16384 + idx]);
                    bool ex = false;
                    for (int kk = 0; kk <= k; kk++)
                        if (stopi[kk] == idx) ex = true;
                    if (!ex && (e > nv || (e == nv && idx < np))) { nv = e; np = idx; }
                }
                #pragma unroll
                for (int off = 16; off; off >>= 1) {
                    float ov = __shfl_xor_sync(0xffffffffu, nv, off);
                    int op = __shfl_xor_sync(0xffffffffu, np, off);
                    if (ov > nv || (ov == nv && op < np)) { nv = ov; np = op; }
                }
                if (tid == 0) { sv[bs][2] = nv; sp[bs][2] = np; scnt[bs] = 2; }
                __syncwarp();
            }
        }
        float pv = expf(topv[tid] - topv[0]);
        float ssum = pv;
        #pragma unroll
        for (int off = 16; off; off >>= 1) ssum += __shfl_xor_sync(0xffffffffu, ssum, off);
        probs[tid] = pv / ssum;
    }
    __syncthreads();

    {
        int d = tid & 63, kq = tid >> 6;
        float acc = 0.f;
        #pragma unroll
        for (int j = 0; j < 8; j++) {
            int k = kq * 8 + j;
            acc += probs[k] * __ldg(&genes[(size_t)stopi[k] * 64 + d]);
        }
        sred[kq][d] = acc;
    }
    __syncthreads();
    if (tid < 64)
        expr[(size_t)t * 64 + tid] = sred[0][tid] + sred[1][tid] + sred[2][tid] + sred[3][tid];
}

// ---------------- kernel 4: down/up + residual (bf16 xn, bf16 weights) -----
__global__ void k_downup(float* __restrict__ x, const __nv_bfloat16* __restrict__ xn,
                         const float* __restrict__ expr,
                         const __nv_bfloat16* __restrict__ g2d,
                         const __nv_bfloat16* __restrict__ g2u,
                         const float* __restrict__ scale_p, int layer) {
    __shared__ float sgd[64][65];
    __shared__ float sgu[64][65];
    __shared__ float sex[16][64];

    int t0 = blockIdx.x * 16;
    int d0 = blockIdx.y * 64;
    int tid = threadIdx.x;
    float s = scale_p[layer];

    // load g2d/g2u tiles: 64x64 bf16 each = 4096 elts = 512 uint4 loads each
    #pragma unroll
    for (int i = 0; i < 2; i++) {
        int sidx = tid + i * 256;          // 0..511 uint4 slots; 8 per row
        int r = sidx >> 3;
        int cc = (sidx & 7) << 3;
        uint4 vd = *reinterpret_cast<const uint4*>(&g2d[(size_t)(d0 + r) * 64 + cc]);
        uint4 vu = *reinterpret_cast<const uint4*>(&g2u[(size_t)(d0 + r) * 64 + cc]);
        const uint32_t* wd = reinterpret_cast<const uint32_t*>(&vd);
        const uint32_t* wu = reinterpret_cast<const uint32_t*>(&vu);
        #pragma unroll
        for (int q = 0; q < 4; q++) {
            __nv_bfloat162 pd = *reinterpret_cast<const __nv_bfloat162*>(&wd[q]);
            __nv_bfloat162 pu = *reinterpret_cast<const __nv_bfloat162*>(&wu[q]);
            sgd[r][cc + q * 2 + 0] = __bfloat162float(pd.x);
            sgd[r][cc + q * 2 + 1] = __bfloat162float(pd.y);
            sgu[r][cc + q * 2 + 0] = __bfloat162float(pu.x);
            sgu[r][cc + q * 2 + 1] = __bfloat162float(pu.y);
        }
    }
    {
        int r = tid >> 4;
        int cc = (tid & 15) << 2;
        float4 ve = *reinterpret_cast<const float4*>(&expr[(size_t)(t0 + r) * 64 + cc]);
        sex[r][cc + 0] = ve.x; sex[r][cc + 1] = ve.y; sex[r][cc + 2] = ve.z; sex[r][cc + 3] = ve.w;
    }
    __syncthreads();

    int d = tid & 63;
    int tg = (tid >> 6) * 4;
    float accd[4] = {0.f, 0.f, 0.f, 0.f};
    float accu[4] = {0.f, 0.f, 0.f, 0.f};
    #pragma unroll
    for (int e = 0; e < 64; e++) {
        float gd = sgd[d][e];
        float gu = sgu[d][e];
        #pragma unroll
        for (int tt = 0; tt < 4; tt++) {
            float ex = sex[tg + tt][e];
            accd[tt] += ex * gd;
            accu[tt] += ex * gu;
        }
    }
    #pragma unroll
    for (int tt = 0; tt < 4; tt++) {
        size_t off = (size_t)(t0 + tg + tt) * 1024 + d0 + d;
        float xnv = __bfloat162float(xn[off]);
        x[off] += tanhf(accd[tt]) * xnv * accu[tt] * s;
    }
}

// ---------------- host-side tensormap construction --------------------------
typedef CUresult (*EncodeTiledFn)(
    CUtensorMap*, CUtensorMapDataType, cuuint32_t, void*,
    const cuuint64_t*, const cuuint64_t*, const cuuint32_t*, const cuuint32_t*,
    CUtensorMapInterleave, CUtensorMapSwizzle, CUtensorMapL2promotion,
    CUtensorMapFloatOOBfill);

static void make_map_16(EncodeTiledFn fn, CUtensorMap* m, const void* ptr,
                        uint64_t rows, CUtensorMapDataType dt) {
    cuuint64_t dims[2] = {1024, rows};
    cuuint64_t strides[1] = {1024 * 2};
    cuuint32_t box[2] = {64, 256};
    cuuint32_t estr[2] = {1, 1};
    fn(m, dt, 2, const_cast<void*>(ptr),
       dims, strides, box, estr,
       CU_TENSOR_MAP_INTERLEAVE_NONE, CU_TENSOR_MAP_SWIZZLE_128B,
       CU_TENSOR_MAP_L2_PROMOTION_L2_128B, CU_TENSOR_MAP_FLOAT_OOB_FILL_NONE);
}

static void make_map_8(EncodeTiledFn fn, CUtensorMap* m, const void* ptr,
                       uint64_t rows) {
    cuuint64_t dims[2] = {1024, rows};
    cuuint64_t strides[1] = {1024};
    cuuint32_t box[2] = {128, 256};
    cuuint32_t estr[2] = {1, 1};
    fn(m, CU_TENSOR_MAP_DATA_TYPE_UINT8, 2, const_cast<void*>(ptr),
       dims, strides, box, estr,
       CU_TENSOR_MAP_INTERLEAVE_NONE, CU_TENSOR_MAP_SWIZZLE_128B,
       CU_TENSOR_MAP_L2_PROMOTION_L2_128B, CU_TENSOR_MAP_FLOAT_OOB_FILL_NONE);
}

// ---------------- launch ----------------------------------------------------
extern "C" void kernel_launch(void* const* d_in, const int* in_sizes, int n_in,
                              void* d_out, int out_size) {
    (void)in_sizes; (void)n_in; (void)out_size;
    const int* ids = (const int*)d_in[0];
    const float* embed = (const float*)d_in[1];
    const float* lm_head = (const float*)d_in[2];
    const float* norm_w = (const float*)d_in[3];
    const float* genes = (const float*)d_in[4];
    const float* ctx_w = (const float*)d_in[5];
    const float* temp = (const float*)d_in[6];
    const float* g2d = (const float*)d_in[7];
    const float* g2u = (const float*)d_in[8];
    const float* lnorm = (const float*)d_in[9];
    const float* scale = (const float*)d_in[10];
    float* out = (float*)d_out;

    float *x, *expr;
    __nv_bfloat16 *logbf, *xnbf, *g2dbf, *g2ubf;
    __half *xnh, *lmwh;
    uint8_t *xnf8, *ctxf8;
    cudaGetSymbolAddress((void**)&x, g_x);
    cudaGetSymbolAddress((void**)&xnbf, g_xn_bf);
    cudaGetSymbolAddress((void**)&xnf8, g_xn_f8);
    cudaGetSymbolAddress((void**)&xnh, g_xn_h);
    cudaGetSymbolAddress((void**)&logbf, g_logits_bf);
    cudaGetSymbolAddress((void**)&expr, g_expr);
    cudaGetSymbolAddress((void**)&lmwh, g_lmw_h);
    cudaGetSymbolAddress((void**)&ctxf8, g_ctxw_f8);
    cudaGetSymbolAddress((void**)&g2dbf, g_g2d_bf);
    cudaGetSymbolAddress((void**)&g2ubf, g_g2u_bf);

    void* fnp = nullptr;
    cudaDriverEntryPointQueryResult qst;
    cudaGetDriverEntryPoint("cuTensorMapEncodeTiled", &fnp, cudaEnableDefault, &qst);
    EncodeTiledFn enc = (EncodeTiledFn)fnp;

    CUtensorMap tmA_f8, tmB_f8[4], tmA_h, tmHead;
    make_map_8(enc, &tmA_f8, xnf8, 2048);
    for (int i = 0; i < 4; i++)
        make_map_8(enc, &tmB_f8[i], ctxf8 + (size_t)i * 16384 * 1024, 16384);
    make_map_16(enc, &tmA_h, xnh, 2048, CU_TENSOR_MAP_DATA_TYPE_FLOAT16);
    make_map_16(enc, &tmHead, lmwh, 32000, CU_TENSOR_MAP_DATA_TYPE_FLOAT16);

    const int GEMM_SMEM = 1024 + 3 * (256 * 128) + 3 * (256 * 128);  // 197632
    cudaFuncSetAttribute(k_gemm_tc, cudaFuncAttributeMaxDynamicSharedMemorySize, GEMM_SMEM);

    // ---- side stream + events (created once) ----
    static cudaStream_t s1 = nullptr;
    static cudaEvent_t ev_fork = nullptr, ev_h = nullptr, ev_gg = nullptr, ev_f8[4] = {};
    if (!s1) {
        cudaStreamCreateWithFlags(&s1, cudaStreamNonBlocking);
        cudaEventCreateWithFlags(&ev_fork, cudaEventDisableTiming);
        cudaEventCreateWithFlags(&ev_h, cudaEventDisableTiming);
        cudaEventCreateWithFlags(&ev_gg, cudaEventDisableTiming);
        for (int i = 0; i < 4; i++)
            cudaEventCreateWithFlags(&ev_f8[i], cudaEventDisableTiming);
    }

    const size_t CHUNK = (size_t)16384 * 1024;
    const int CHUNK_BLOCKS = (int)(CHUNK / 2048);
    const int GG_BLOCKS = 4 * 1024 * 64 / 2048;   // 128

    cudaEventRecord(ev_fork, 0);
    cudaStreamWaitEvent(s1, ev_fork, 0);

    // side stream: chunk0 first (earliest consumer), then g2d/g2u, rest, lm_head
    k_cvt_f8<<<CHUNK_BLOCKS, 256, 0, s1>>>(ctx_w, ctxf8);
    cudaEventRecord(ev_f8[0], s1);
    k_cvt_bf<<<GG_BLOCKS, 256, 0, s1>>>(g2d, g2dbf);
    k_cvt_bf<<<GG_BLOCKS, 256, 0, s1>>>(g2u, g2ubf);
    cudaEventRecord(ev_gg, s1);
    for (int c = 1; c < 4; c++) {
        k_cvt_f8<<<CHUNK_BLOCKS, 256, 0, s1>>>(ctx_w + (size_t)c * CHUNK,
                                               ctxf8 + (size_t)c * CHUNK);
        cudaEventRecord(ev_f8[c], s1);
    }
    k_cvt_h<<<16000, 256, 0, s1>>>(lm_head, lmwh);
    cudaEventRecord(ev_h, s1);

    const float inv_presc = 1.0f / WEIGHT_PRESCALE;
    for (int i = 0; i < 4; i++) {
        k_rmsnorm<<<2048, 256>>>(ids, embed, x, lnorm + (size_t)i * 1024,
                                 xnbf, xnf8, nullptr, i == 0 ? 2 : 0);
        cudaStreamWaitEvent(0, ev_f8[i], 0);
        dim3 g1(16384 / 256, 2048 / 256);
        k_gemm_tc<<<g1, 288, GEMM_SMEM>>>(tmA_f8, tmB_f8[i], nullptr, logbf, 16384,
                                          temp, i, inv_presc, 8, 128, 1, 1);
        k_topk_express<<<2048, 256>>>(logbf, genes, expr);
        if (i == 0) cudaStreamWaitEvent(0, ev_gg, 0);
        dim3 g2(2048 / 16, 1024 / 64);
        k_downup<<<g2, 256>>>(x, xnbf, expr, g2dbf + (size_t)i * 1024 * 64,
                              g2ubf + (size_t)i * 1024 * 64, scale, i);
    }

    k_rmsnorm<<<2048, 256>>>(ids, embed, x, norm_w, nullptr, nullptr,
                             (uint16_t*)xnh, 1);
    cudaStreamWaitEvent(0, ev_h, 0);
    dim3 g3(32000 / 256, 2048 / 256);
    k_gemm_tc<<<g3, 288, GEMM_SMEM>>>(tmA_h, tmHead, out, nullptr, 32000,
                                      nullptr, 0, 1.0f, 16, 64, 0, 0);
}